// round 11
// baseline (speedup 1.0000x reference)
#include <cuda_runtime.h>
#include <cuda_fp16.h>
#include <math.h>
#include <stdint.h>

#define T_TOK 65536      // B * (H/2) * (W/2)
#define K_REAL 1156
#define HID 1024
#define NOUT 256

// ---------------- scratch (device globals; allocation-free) ----------------
__device__ __align__(16) __half g_Hh[(size_t)T_TOK * HID];
__device__ __align__(16) __half g_W2h[NOUT * HID];
__device__ __align__(16) float g_U[16 * 4 * HID];        // [b][s][n]
__device__ __align__(16) float g_CX[16 * 4 * 64 * HID];  // [b][s][j][n]
__device__ __align__(16) float g_CY[16 * 4 * 64 * HID];  // [b][s][i][n]

// ---------------- PTX helpers (baseline PTX only) ----------------
__device__ __forceinline__ uint32_t smem_u32(const void* p) {
    uint32_t a;
    asm("{ .reg .u64 t; cvta.to.shared.u64 t, %1; cvt.u32.u64 %0, t; }"
        : "=r"(a) : "l"(p));
    return a;
}
__device__ __forceinline__ void cp_async16(uint32_t dst, const void* src) {
    asm volatile("cp.async.cg.shared.global [%0], [%1], 16;"
                 :: "r"(dst), "l"(src));
}
#define CP_COMMIT() asm volatile("cp.async.commit_group;" ::: "memory")
#define CP_WAIT(n)  asm volatile("cp.async.wait_group %0;" :: "n"(n) : "memory")

__device__ __forceinline__ void ldsm_x4(uint32_t* r, uint32_t addr) {
    asm volatile("ldmatrix.sync.aligned.m8n8.x4.shared.b16 {%0,%1,%2,%3}, [%4];"
                 : "=r"(r[0]), "=r"(r[1]), "=r"(r[2]), "=r"(r[3]) : "r"(addr));
}
__device__ __forceinline__ void mma_f16(float* d, const uint32_t* a,
                                        uint32_t b0, uint32_t b1) {
    asm volatile("mma.sync.aligned.m16n8k16.row.col.f32.f16.f16.f32 "
                 "{%0,%1,%2,%3}, {%4,%5,%6,%7}, {%8,%9}, {%0,%1,%2,%3};"
                 : "+f"(d[0]), "+f"(d[1]), "+f"(d[2]), "+f"(d[3])
                 : "r"(a[0]), "r"(a[1]), "r"(a[2]), "r"(a[3]), "r"(b0), "r"(b1));
}
// pack two fp32 -> fp16x2 (lo = first arg)
__device__ __forceinline__ uint32_t pack_f16x2(float lo, float hi) {
    uint32_t r;
    asm("cvt.rn.f16x2.f32 %0, %1, %2;" : "=r"(r) : "f"(hi), "f"(lo));
    return r;
}

// ---------------------------------------------------------------------------
// Launch 1: CX/CY with inline cos table (bit-exact fp32 arg chain + double cos)
// ---------------------------------------------------------------------------
__global__ void cxy_kernel(const float* __restrict__ w1,
                           const float* __restrict__ pos) {
    __shared__ float scos[1024];   // [f][j] for this (ax, b, sub)
    int n = blockIdx.x * 256 + threadIdx.x;
    int s = blockIdx.y;
    int bz = blockIdx.z;
    int b = bz & 15;
    int ax = bz >> 4;
    int sub = ax ? (s >> 1) : (s & 1);

    {
        const float HALF_PI = 1.57079632679489661923f;
        float pw = pos[b * 4 + 3];
        float stdv = __fdiv_rn(0.1f, fminf(fmaxf(pw, 0.0078125f), 0.5f));
        float ctr = fminf(fmaxf(pos[b * 4 + (ax ? 1 : 0)], -1.f), 1.f);
#pragma unroll
        for (int k = 0; k < 4; k++) {
            int idx = threadIdx.x + k * 256;
            int f = idx >> 6;
            int j = idx & 63;
            int w = 2 * j + sub;
            float g = __fsub_rn(__fmul_rn(__fdiv_rn((float)w, 127.0f), 2.0f), 1.0f);
            float fs = (float)(1 << f);
            float a = __fmul_rn(__fmul_rn(__fmul_rn(__fsub_rn(g, ctr), stdv), HALF_PI), fs);
            scos[idx] = (float)cos((double)a);
        }
    }
    __syncthreads();

    float w[16];
    size_t base = (size_t)n * K_REAL + 1024 + (ax ? 4 : 0) + s;
#pragma unroll
    for (int f = 0; f < 16; f++) w[f] = w1[base + 8 * f];
    float* outp = (ax ? g_CY : g_CX) + ((size_t)(b * 4 + s) * 64) * HID + n;
#pragma unroll 2
    for (int j = 0; j < 64; j++) {
        float acc = 0.f;
#pragma unroll
        for (int f = 0; f < 16; f++) acc += w[f] * scos[f * 64 + j];
        outp[(size_t)j * HID] = acc;
    }
}

// ---------------------------------------------------------------------------
// Launch 2: misc = U fold (blocks 0..63) + W2 fp16 convert (blocks 64..)
// ---------------------------------------------------------------------------
__global__ void misc_kernel(const float* __restrict__ w1,
                            const float* __restrict__ gestalt,
                            const float* __restrict__ w2) {
    int bx = blockIdx.x;
    if (bx < 64) {
        int n = (bx & 3) * 256 + threadIdx.x;
        int b = bx >> 2;
        const float4* wrow = (const float4*)(w1 + (size_t)n * K_REAL);
        const float* g = gestalt + b * 256;
        float a0 = 0.f, a1 = 0.f, a2 = 0.f, a3 = 0.f;
#pragma unroll 4
        for (int c = 0; c < 256; c++) {
            float4 w = wrow[c];
            float gv = g[c];
            a0 += w.x * gv; a1 += w.y * gv; a2 += w.z * gv; a3 += w.w * gv;
        }
        g_U[(b * 4 + 0) * HID + n] = a0;
        g_U[(b * 4 + 1) * HID + n] = a1;
        g_U[(b * 4 + 2) * HID + n] = a2;
        g_U[(b * 4 + 3) * HID + n] = a3;
    } else {
        int idx = (bx - 64) * 256 + threadIdx.x;
        if (idx < NOUT * HID) g_W2h[idx] = __float2half_rn(w2[idx]);
    }
}

// ---------------------------------------------------------------------------
// Launch 3: Fused H, i-split 4-way for wave balance (verified R10).
// ---------------------------------------------------------------------------
#define FH_SMEM (10528 * 4)

__global__ __launch_bounds__(256, 3) void fused_h_kernel(
    const float* __restrict__ mask, const float* __restrict__ depth,
    const float* __restrict__ w1, const float* __restrict__ b1) {
    extern __shared__ float sm[];
    float* sCX = sm;              // [s][j(64)][nl(32)]
    float* sCY = sm + 8192;       // [s][il(16)][nl(32)]
    float* sU  = sm + 10240;      // [s][nl]
    float* sWd = sm + 10368;      // [s][nl]
    float* sB  = sm + 10496;      // [nl]

    const int b  = blockIdx.y;
    const int n0 = blockIdx.x * 32;
    const int iz = blockIdx.z;
    const int tid = threadIdx.x;

    for (int idx = tid; idx < 8192; idx += 256) {
        int nl = idx & 31, j = (idx >> 5) & 63, s = idx >> 11;
        sCX[idx] = g_CX[((size_t)(b * 4 + s) * 64 + j) * HID + n0 + nl];
    }
    for (int idx = tid; idx < 2048; idx += 256) {
        int nl = idx & 31, il = (idx >> 5) & 15, s = idx >> 9;
        sCY[idx] = g_CY[((size_t)(b * 4 + s) * 64 + iz * 16 + il) * HID + n0 + nl];
    }
    if (tid < 128) {
        int s = tid >> 5, nl = tid & 31;
        sU[tid]  = g_U[(b * 4 + s) * HID + n0 + nl];
        sWd[tid] = w1[(size_t)(n0 + nl) * K_REAL + 1152 + s];
    }
    if (tid < 32) sB[tid] = b1[n0 + tid];
    __syncthreads();

    const int npl = (tid & 7) * 4;     // 4 consecutive n
    const int tg  = tid >> 3;          // 0..31
    const int il  = tg & 15;           // i within split
    const int jh  = tg >> 4;           // j half (0/1)
    const int i   = iz * 16 + il;

    float uc[4][4], wds[4][4], bbs[4];
#pragma unroll
    for (int s = 0; s < 4; s++) {
        float4 tu = *(float4*)&sU[s * 32 + npl];
        float4 tc = *(float4*)&sCY[s * 512 + il * 32 + npl];
        uc[s][0] = tu.x + tc.x; uc[s][1] = tu.y + tc.y;
        uc[s][2] = tu.z + tc.z; uc[s][3] = tu.w + tc.w;
        float4 tw = *(float4*)&sWd[s * 32 + npl];
        wds[s][0] = tw.x; wds[s][1] = tw.y; wds[s][2] = tw.z; wds[s][3] = tw.w;
    }
    {
        float4 tb = *(float4*)&sB[npl];
        bbs[0] = tb.x; bbs[1] = tb.y; bbs[2] = tb.z; bbs[3] = tb.w;
    }

    const float* mrow = mask  + b * 16384 + i * 256 + jh * 64;
    const float* drow = depth + b * 16384 + i * 256 + jh * 64;
    const float* cxb  = sCX + (jh * 32) * 32 + npl;
    size_t rowbase = ((size_t)(b * 4096 + i * 64 + jh * 32)) * HID + n0 + npl;

#pragma unroll 4
    for (int jp = 0; jp < 16; jp++) {      // 2 j per iteration
        float4 mv0 = *(const float4*)&mrow[jp * 4];
        float4 mv1 = *(const float4*)&mrow[jp * 4 + 128];
        float4 dv0 = *(const float4*)&drow[jp * 4];
        float4 dv1 = *(const float4*)&drow[jp * 4 + 128];
#pragma unroll
        for (int t = 0; t < 2; t++) {
            float m00 = t ? mv0.z : mv0.x;
            float m01 = t ? mv0.w : mv0.y;
            float m10 = t ? mv1.z : mv1.x;
            float m11 = t ? mv1.w : mv1.y;
            float d00 = t ? dv0.z : dv0.x;
            float d01 = t ? dv0.w : dv0.y;
            float d10 = t ? dv1.z : dv1.x;
            float d11 = t ? dv1.w : dv1.y;
            int jl = jp * 2 + t;
            float4 cx0 = *(float4*)&cxb[0 * 2048 + jl * 32];
            float4 cx1 = *(float4*)&cxb[1 * 2048 + jl * 32];
            float4 cx2 = *(float4*)&cxb[2 * 2048 + jl * 32];
            float4 cx3 = *(float4*)&cxb[3 * 2048 + jl * 32];
            float cxs[4][4];
            cxs[0][0] = cx0.x; cxs[0][1] = cx0.y; cxs[0][2] = cx0.z; cxs[0][3] = cx0.w;
            cxs[1][0] = cx1.x; cxs[1][1] = cx1.y; cxs[1][2] = cx1.z; cxs[1][3] = cx1.w;
            cxs[2][0] = cx2.x; cxs[2][1] = cx2.y; cxs[2][2] = cx2.z; cxs[2][3] = cx2.w;
            cxs[3][0] = cx3.x; cxs[3][1] = cx3.y; cxs[3][2] = cx3.z; cxs[3][3] = cx3.w;
            float v[4];
#pragma unroll
            for (int q = 0; q < 4; q++) {
                float h = bbs[q];
                h += m00 * (uc[0][q] + cxs[0][q] + d00 * wds[0][q]);
                h += m01 * (uc[1][q] + cxs[1][q] + d01 * wds[1][q]);
                h += m10 * (uc[2][q] + cxs[2][q] + d10 * wds[2][q]);
                h += m11 * (uc[3][q] + cxs[3][q] + d11 * wds[3][q]);
                v[q] = __fdividef(h, 1.0f + __expf(-h));
            }
            uint2 o;
            o.x = pack_f16x2(v[0], v[1]);
            o.y = pack_f16x2(v[2], v[3]);
            __stcs((uint2*)(g_Hh + rowbase + (size_t)jl * HID), o);
        }
    }
}

// ---------------------------------------------------------------------------
// Launch 4 (ncu slot): single-pass fp16 GEMM, BK=64, 3-stage pipeline.
// CTA 128x128, 8 warps (4Mx2N). 16 K-iters, one sync per iter,
// 4 ks-bursts (64 mma/warp) between syncs.
// ---------------------------------------------------------------------------
#define BM 128
#define BN 128
#define BK 64
#define ROWB 144                 // 128B data + 16B pad (bank-conflict-free ldsm)
#define TILE_B (BM * ROWB)       // 18432
#define OFF_A 0
#define OFF_B TILE_B
#define STAGE_B (2 * TILE_B)     // 36864
#define NSTAGE 3
#define SMEM_DYN (NSTAGE * STAGE_B)  // 110592

__device__ __forceinline__ void cp_chunk(uint32_t st,
                                         const __half* A, const __half* B,
                                         int K, int k0, int tid) {
#pragma unroll
    for (int it = 0; it < 4; it++) {
        int idx = tid + it * 256;         // 0..1023
        int r = idx >> 3, q = idx & 7;    // row 0..127, 16B seg 0..7
        uint32_t o = (uint32_t)(r * ROWB + q * 16);
        size_t so = (size_t)r * K + k0 + q * 8;
        cp_async16(st + OFF_A + o, A + so);
        cp_async16(st + OFF_B + o, B + so);
    }
}

__global__ __launch_bounds__(256, 2) void gemm2_f16(
    const __half* __restrict__ A_g, const __half* __restrict__ B_g,
    int K, int NCH, const float* __restrict__ bias, float* __restrict__ outp) {
    extern __shared__ char dsm[];
    uint32_t sb = smem_u32(dsm);

    const int tid = threadIdx.x;
    const int wid = tid >> 5;
    const int L = tid & 31;
    const int m0 = blockIdx.y * BM;
    const int n0 = blockIdx.x * BN;
    const int warp_m = (wid >> 1) * 32;
    const int warp_n = (wid & 1) * 64;

    const __half* A = A_g + (size_t)m0 * K;
    const __half* B = B_g + (size_t)n0 * K;

    const int rowA = warp_m + (L & 7) + ((L >> 3) & 1) * 8;
    const int colA = (L >> 4) * 8;
    const int rowB = warp_n + (L & 7) + (L >> 4) * 8;
    const int colB = ((L >> 3) & 1) * 8;

    float d[2][8][4];
#pragma unroll
    for (int i = 0; i < 2; i++)
#pragma unroll
        for (int j = 0; j < 8; j++)
#pragma unroll
            for (int e = 0; e < 4; e++) d[i][j][e] = 0.0f;

    // prefetch stages 0..1
#pragma unroll
    for (int p = 0; p < NSTAGE - 1; p++) {
        cp_chunk(sb + p * STAGE_B, A, B, K, p * BK, tid);
        CP_COMMIT();
    }

    int stage = 0;
    for (int c = 0; c < NCH; c++) {
        // wait for chunk c (in-flight after: c+1 if it exists)
        if (c + 1 < NCH) { CP_WAIT(1); } else { CP_WAIT(0); }
        __syncthreads();
        // issue chunk c+2 into slot consumed at iter c-1 (safe after the sync)
        if (c + NSTAGE - 1 < NCH) {
            int ps = stage + NSTAGE - 1; if (ps >= NSTAGE) ps -= NSTAGE;
            cp_chunk(sb + ps * STAGE_B, A, B, K, (c + NSTAGE - 1) * BK, tid);
            CP_COMMIT();
        }

        uint32_t st = sb + stage * STAGE_B;
#pragma unroll
        for (int ks = 0; ks < 4; ks++) {
            uint32_t aoff = (uint32_t)((ks * 16 + colA) * 2);
            uint32_t boff = (uint32_t)((ks * 16 + colB) * 2);
            uint32_t ah[2][4], bh[4][4];
#pragma unroll
            for (int mt = 0; mt < 2; mt++)
                ldsm_x4(ah[mt], st + OFF_A + (uint32_t)((rowA + mt * 16) * ROWB) + aoff);
#pragma unroll
            for (int np = 0; np < 4; np++)
                ldsm_x4(bh[np], st + OFF_B + (uint32_t)((rowB + np * 16) * ROWB) + boff);
#pragma unroll
            for (int mt = 0; mt < 2; mt++)
#pragma unroll
                for (int np = 0; np < 4; np++) {
                    mma_f16(d[mt][np * 2],     ah[mt], bh[np][0], bh[np][1]);
                    mma_f16(d[mt][np * 2 + 1], ah[mt], bh[np][2], bh[np][3]);
                }
        }
        stage++; if (stage >= NSTAGE) stage = 0;
    }

#pragma unroll
    for (int mt = 0; mt < 2; mt++) {
#pragma unroll
        for (int np = 0; np < 4; np++) {
#pragma unroll
            for (int o = 0; o < 2; o++) {
                const float* dd = d[mt][np * 2 + o];
                int nb = n0 + warp_n + np * 16 + o * 8 + 2 * (L & 3);
                float bv0 = __ldg(bias + nb);
                float bv1 = __ldg(bias + nb + 1);
#pragma unroll
                for (int h = 0; h < 2; h++) {
                    int m = m0 + warp_m + mt * 16 + (L >> 2) + h * 8;
                    size_t obase = ((size_t)(m >> 12) << 20) + (size_t)(m & 4095);
                    __stcs(outp + obase + ((size_t)nb << 12), dd[2 * h] + bv0);
                    __stcs(outp + obase + ((size_t)(nb + 1) << 12), dd[2 * h + 1] + bv1);
                }
            }
        }
    }
}

// ---------------------------------------------------------------------------
extern "C" void kernel_launch(void* const* d_in, const int* in_sizes, int n_in,
                              void* d_out, int out_size) {
    const float* position = (const float*)d_in[0];
    const float* gestalt  = (const float*)d_in[1];
    const float* mask     = (const float*)d_in[2];
    const float* depth    = (const float*)d_in[3];
    const float* w1       = (const float*)d_in[4];
    const float* b1       = (const float*)d_in[5];
    const float* w2       = (const float*)d_in[6];
    const float* b2       = (const float*)d_in[7];
    float* out = (float*)d_out;
    (void)in_sizes; (void)n_in; (void)out_size;

    cudaFuncSetAttribute(gemm2_f16, cudaFuncAttributeMaxDynamicSharedMemorySize, SMEM_DYN);
    cudaFuncSetAttribute(fused_h_kernel, cudaFuncAttributeMaxDynamicSharedMemorySize, FH_SMEM);

    __half *w2h, *hh;
    cudaGetSymbolAddress((void**)&w2h, g_W2h);
    cudaGetSymbolAddress((void**)&hh, g_Hh);

    // Launch 1: CX/CY (inline cos)
    cxy_kernel<<<dim3(4, 4, 32), 256>>>(w1, position);
    // Launch 2: U fold + W2 convert (merged)
    misc_kernel<<<64 + (NOUT * HID + 255) / 256, 256>>>(w1, gestalt, w2);
    // Launch 3: fused H (i-split 4-way)
    fused_h_kernel<<<dim3(32, 16, 4), 256, FH_SMEM>>>(mask, depth, w1, b1);
    // Launch 4 (ncu capture slot): gemm2, BK=64 3-stage
    dim3 grid2(NOUT / BN, T_TOK / BM);  // (2, 512)
    gemm2_f16<<<grid2, 256, SMEM_DYN>>>(hh, w2h, HID, HID / BK, b2, out);
}

// round 12
// speedup vs baseline: 1.1766x; 1.1766x over previous
#include <cuda_runtime.h>
#include <cuda_fp16.h>
#include <math.h>
#include <stdint.h>

#define T_TOK 65536      // B * (H/2) * (W/2)
#define K_REAL 1156
#define HID 1024
#define NOUT 256

// ---------------- scratch (device globals; allocation-free) ----------------
__device__ __align__(16) __half g_Hh[(size_t)T_TOK * HID];
__device__ __align__(16) __half g_W2h[NOUT * HID];
__device__ __align__(16) float g_U[16 * 4 * HID];        // [b][s][n]
__device__ __align__(16) float g_CX[16 * 4 * 64 * HID];  // [b][s][j][n]
__device__ __align__(16) float g_CY[16 * 4 * 64 * HID];  // [b][s][i][n]

// ---------------- PTX helpers (baseline PTX only) ----------------
__device__ __forceinline__ uint32_t smem_u32(const void* p) {
    uint32_t a;
    asm("{ .reg .u64 t; cvta.to.shared.u64 t, %1; cvt.u32.u64 %0, t; }"
        : "=r"(a) : "l"(p));
    return a;
}
__device__ __forceinline__ void cp_async16(uint32_t dst, const void* src) {
    asm volatile("cp.async.cg.shared.global [%0], [%1], 16;"
                 :: "r"(dst), "l"(src));
}
#define CP_COMMIT() asm volatile("cp.async.commit_group;" ::: "memory")
#define CP_WAIT(n)  asm volatile("cp.async.wait_group %0;" :: "n"(n) : "memory")

__device__ __forceinline__ void ldsm_x4(uint32_t* r, uint32_t addr) {
    asm volatile("ldmatrix.sync.aligned.m8n8.x4.shared.b16 {%0,%1,%2,%3}, [%4];"
                 : "=r"(r[0]), "=r"(r[1]), "=r"(r[2]), "=r"(r[3]) : "r"(addr));
}
__device__ __forceinline__ void mma_f16(float* d, const uint32_t* a,
                                        uint32_t b0, uint32_t b1) {
    asm volatile("mma.sync.aligned.m16n8k16.row.col.f32.f16.f16.f32 "
                 "{%0,%1,%2,%3}, {%4,%5,%6,%7}, {%8,%9}, {%0,%1,%2,%3};"
                 : "+f"(d[0]), "+f"(d[1]), "+f"(d[2]), "+f"(d[3])
                 : "r"(a[0]), "r"(a[1]), "r"(a[2]), "r"(a[3]), "r"(b0), "r"(b1));
}
// pack two fp32 -> fp16x2 (lo = first arg)
__device__ __forceinline__ uint32_t pack_f16x2(float lo, float hi) {
    uint32_t r;
    asm("cvt.rn.f16x2.f32 %0, %1, %2;" : "=r"(r) : "f"(hi), "f"(lo));
    return r;
}

// ---------------------------------------------------------------------------
// Launch 1: CX/CY with inline cos table (bit-exact fp32 arg chain + double cos)
// ---------------------------------------------------------------------------
__global__ void cxy_kernel(const float* __restrict__ w1,
                           const float* __restrict__ pos) {
    __shared__ float scos[1024];   // [f][j] for this (ax, b, sub)
    int n = blockIdx.x * 256 + threadIdx.x;
    int s = blockIdx.y;
    int bz = blockIdx.z;
    int b = bz & 15;
    int ax = bz >> 4;
    int sub = ax ? (s >> 1) : (s & 1);

    {
        const float HALF_PI = 1.57079632679489661923f;
        float pw = pos[b * 4 + 3];
        float stdv = __fdiv_rn(0.1f, fminf(fmaxf(pw, 0.0078125f), 0.5f));
        float ctr = fminf(fmaxf(pos[b * 4 + (ax ? 1 : 0)], -1.f), 1.f);
#pragma unroll
        for (int k = 0; k < 4; k++) {
            int idx = threadIdx.x + k * 256;
            int f = idx >> 6;
            int j = idx & 63;
            int w = 2 * j + sub;
            float g = __fsub_rn(__fmul_rn(__fdiv_rn((float)w, 127.0f), 2.0f), 1.0f);
            float fs = (float)(1 << f);
            float a = __fmul_rn(__fmul_rn(__fmul_rn(__fsub_rn(g, ctr), stdv), HALF_PI), fs);
            scos[idx] = (float)cos((double)a);
        }
    }
    __syncthreads();

    float w[16];
    size_t base = (size_t)n * K_REAL + 1024 + (ax ? 4 : 0) + s;
#pragma unroll
    for (int f = 0; f < 16; f++) w[f] = w1[base + 8 * f];
    float* outp = (ax ? g_CY : g_CX) + ((size_t)(b * 4 + s) * 64) * HID + n;
#pragma unroll 2
    for (int j = 0; j < 64; j++) {
        float acc = 0.f;
#pragma unroll
        for (int f = 0; f < 16; f++) acc += w[f] * scos[f * 64 + j];
        outp[(size_t)j * HID] = acc;
    }
}

// ---------------------------------------------------------------------------
// Launch 2: misc = U fold (blocks 0..63) + W2 fp16 convert (blocks 64..)
// ---------------------------------------------------------------------------
__global__ void misc_kernel(const float* __restrict__ w1,
                            const float* __restrict__ gestalt,
                            const float* __restrict__ w2) {
    int bx = blockIdx.x;
    if (bx < 64) {
        int n = (bx & 3) * 256 + threadIdx.x;
        int b = bx >> 2;
        const float4* wrow = (const float4*)(w1 + (size_t)n * K_REAL);
        const float* g = gestalt + b * 256;
        float a0 = 0.f, a1 = 0.f, a2 = 0.f, a3 = 0.f;
#pragma unroll 4
        for (int c = 0; c < 256; c++) {
            float4 w = wrow[c];
            float gv = g[c];
            a0 += w.x * gv; a1 += w.y * gv; a2 += w.z * gv; a3 += w.w * gv;
        }
        g_U[(b * 4 + 0) * HID + n] = a0;
        g_U[(b * 4 + 1) * HID + n] = a1;
        g_U[(b * 4 + 2) * HID + n] = a2;
        g_U[(b * 4 + 3) * HID + n] = a3;
    } else {
        int idx = (bx - 64) * 256 + threadIdx.x;
        if (idx < NOUT * HID) g_W2h[idx] = __float2half_rn(w2[idx]);
    }
}

// ---------------------------------------------------------------------------
// Launch 3: Fused H, i-split 4-way (exact R10 body, unroll 2 — verified 100us)
// ---------------------------------------------------------------------------
#define FH_SMEM (10528 * 4)

__global__ __launch_bounds__(256, 3) void fused_h_kernel(
    const float* __restrict__ mask, const float* __restrict__ depth,
    const float* __restrict__ w1, const float* __restrict__ b1) {
    extern __shared__ float sm[];
    float* sCX = sm;              // [s][j(64)][nl(32)]
    float* sCY = sm + 8192;       // [s][il(16)][nl(32)]
    float* sU  = sm + 10240;      // [s][nl]
    float* sWd = sm + 10368;      // [s][nl]
    float* sB  = sm + 10496;      // [nl]

    const int b  = blockIdx.y;
    const int n0 = blockIdx.x * 32;
    const int iz = blockIdx.z;
    const int tid = threadIdx.x;

    for (int idx = tid; idx < 8192; idx += 256) {
        int nl = idx & 31, j = (idx >> 5) & 63, s = idx >> 11;
        sCX[idx] = g_CX[((size_t)(b * 4 + s) * 64 + j) * HID + n0 + nl];
    }
    for (int idx = tid; idx < 2048; idx += 256) {
        int nl = idx & 31, il = (idx >> 5) & 15, s = idx >> 9;
        sCY[idx] = g_CY[((size_t)(b * 4 + s) * 64 + iz * 16 + il) * HID + n0 + nl];
    }
    if (tid < 128) {
        int s = tid >> 5, nl = tid & 31;
        sU[tid]  = g_U[(b * 4 + s) * HID + n0 + nl];
        sWd[tid] = w1[(size_t)(n0 + nl) * K_REAL + 1152 + s];
    }
    if (tid < 32) sB[tid] = b1[n0 + tid];
    __syncthreads();

    const int npl = (tid & 7) * 4;     // 4 consecutive n
    const int tg  = tid >> 3;          // 0..31
    const int il  = tg & 15;           // i within split
    const int jh  = tg >> 4;           // j half (0/1)
    const int i   = iz * 16 + il;

    float uc[4][4], wds[4][4], bbs[4];
#pragma unroll
    for (int s = 0; s < 4; s++) {
        float4 tu = *(float4*)&sU[s * 32 + npl];
        float4 tc = *(float4*)&sCY[s * 512 + il * 32 + npl];
        uc[s][0] = tu.x + tc.x; uc[s][1] = tu.y + tc.y;
        uc[s][2] = tu.z + tc.z; uc[s][3] = tu.w + tc.w;
        float4 tw = *(float4*)&sWd[s * 32 + npl];
        wds[s][0] = tw.x; wds[s][1] = tw.y; wds[s][2] = tw.z; wds[s][3] = tw.w;
    }
    {
        float4 tb = *(float4*)&sB[npl];
        bbs[0] = tb.x; bbs[1] = tb.y; bbs[2] = tb.z; bbs[3] = tb.w;
    }

    const float* mrow = mask  + b * 16384 + i * 256 + jh * 64;
    const float* drow = depth + b * 16384 + i * 256 + jh * 64;
    const float* cxb  = sCX + (jh * 32) * 32 + npl;
    size_t rowbase = ((size_t)(b * 4096 + i * 64 + jh * 32)) * HID + n0 + npl;

#pragma unroll 2
    for (int jp = 0; jp < 16; jp++) {      // 2 j per iteration
        float4 mv0 = *(const float4*)&mrow[jp * 4];
        float4 mv1 = *(const float4*)&mrow[jp * 4 + 128];
        float4 dv0 = *(const float4*)&drow[jp * 4];
        float4 dv1 = *(const float4*)&drow[jp * 4 + 128];
#pragma unroll
        for (int t = 0; t < 2; t++) {
            float m00 = t ? mv0.z : mv0.x;
            float m01 = t ? mv0.w : mv0.y;
            float m10 = t ? mv1.z : mv1.x;
            float m11 = t ? mv1.w : mv1.y;
            float d00 = t ? dv0.z : dv0.x;
            float d01 = t ? dv0.w : dv0.y;
            float d10 = t ? dv1.z : dv1.x;
            float d11 = t ? dv1.w : dv1.y;
            int jl = jp * 2 + t;
            float4 cx0 = *(float4*)&cxb[0 * 2048 + jl * 32];
            float4 cx1 = *(float4*)&cxb[1 * 2048 + jl * 32];
            float4 cx2 = *(float4*)&cxb[2 * 2048 + jl * 32];
            float4 cx3 = *(float4*)&cxb[3 * 2048 + jl * 32];
            float cxs[4][4];
            cxs[0][0] = cx0.x; cxs[0][1] = cx0.y; cxs[0][2] = cx0.z; cxs[0][3] = cx0.w;
            cxs[1][0] = cx1.x; cxs[1][1] = cx1.y; cxs[1][2] = cx1.z; cxs[1][3] = cx1.w;
            cxs[2][0] = cx2.x; cxs[2][1] = cx2.y; cxs[2][2] = cx2.z; cxs[2][3] = cx2.w;
            cxs[3][0] = cx3.x; cxs[3][1] = cx3.y; cxs[3][2] = cx3.z; cxs[3][3] = cx3.w;
            float v[4];
#pragma unroll
            for (int q = 0; q < 4; q++) {
                float h = bbs[q];
                h += m00 * (uc[0][q] + cxs[0][q] + d00 * wds[0][q]);
                h += m01 * (uc[1][q] + cxs[1][q] + d01 * wds[1][q]);
                h += m10 * (uc[2][q] + cxs[2][q] + d10 * wds[2][q]);
                h += m11 * (uc[3][q] + cxs[3][q] + d11 * wds[3][q]);
                v[q] = __fdividef(h, 1.0f + __expf(-h));
            }
            uint2 o;
            o.x = pack_f16x2(v[0], v[1]);
            o.y = pack_f16x2(v[2], v[3]);
            __stcs((uint2*)(g_Hh + rowbase + (size_t)jl * HID), o);
        }
    }
}

// ---------------------------------------------------------------------------
// Launch 4 (ncu slot): single-pass fp16 GEMM, BK=64, 3-stage (verified R11,
// 104us). CTA 128x128, 8 warps (4Mx2N). 16 K-iters, one sync per iter.
// ---------------------------------------------------------------------------
#define BM 128
#define BN 128
#define BK 64
#define ROWB 144                 // 128B data + 16B pad
#define TILE_B (BM * ROWB)       // 18432
#define OFF_A 0
#define OFF_B TILE_B
#define STAGE_B (2 * TILE_B)     // 36864
#define NSTAGE 3
#define SMEM_DYN (NSTAGE * STAGE_B)  // 110592

__device__ __forceinline__ void cp_chunk(uint32_t st,
                                         const __half* A, const __half* B,
                                         int K, int k0, int tid) {
#pragma unroll
    for (int it = 0; it < 4; it++) {
        int idx = tid + it * 256;         // 0..1023
        int r = idx >> 3, q = idx & 7;    // row 0..127, 16B seg 0..7
        uint32_t o = (uint32_t)(r * ROWB + q * 16);
        size_t so = (size_t)r * K + k0 + q * 8;
        cp_async16(st + OFF_A + o, A + so);
        cp_async16(st + OFF_B + o, B + so);
    }
}

__global__ __launch_bounds__(256, 2) void gemm2_f16(
    const __half* __restrict__ A_g, const __half* __restrict__ B_g,
    int K, int NCH, const float* __restrict__ bias, float* __restrict__ outp) {
    extern __shared__ char dsm[];
    uint32_t sb = smem_u32(dsm);

    const int tid = threadIdx.x;
    const int wid = tid >> 5;
    const int L = tid & 31;
    const int m0 = blockIdx.y * BM;
    const int n0 = blockIdx.x * BN;
    const int warp_m = (wid >> 1) * 32;
    const int warp_n = (wid & 1) * 64;

    const __half* A = A_g + (size_t)m0 * K;
    const __half* B = B_g + (size_t)n0 * K;

    const int rowA = warp_m + (L & 7) + ((L >> 3) & 1) * 8;
    const int colA = (L >> 4) * 8;
    const int rowB = warp_n + (L & 7) + (L >> 4) * 8;
    const int colB = ((L >> 3) & 1) * 8;

    float d[2][8][4];
#pragma unroll
    for (int i = 0; i < 2; i++)
#pragma unroll
        for (int j = 0; j < 8; j++)
#pragma unroll
            for (int e = 0; e < 4; e++) d[i][j][e] = 0.0f;

#pragma unroll
    for (int p = 0; p < NSTAGE - 1; p++) {
        cp_chunk(sb + p * STAGE_B, A, B, K, p * BK, tid);
        CP_COMMIT();
    }

    int stage = 0;
    for (int c = 0; c < NCH; c++) {
        if (c + 1 < NCH) { CP_WAIT(1); } else { CP_WAIT(0); }
        __syncthreads();
        if (c + NSTAGE - 1 < NCH) {
            int ps = stage + NSTAGE - 1; if (ps >= NSTAGE) ps -= NSTAGE;
            cp_chunk(sb + ps * STAGE_B, A, B, K, (c + NSTAGE - 1) * BK, tid);
            CP_COMMIT();
        }

        uint32_t st = sb + stage * STAGE_B;
#pragma unroll
        for (int ks = 0; ks < 4; ks++) {
            uint32_t aoff = (uint32_t)((ks * 16 + colA) * 2);
            uint32_t boff = (uint32_t)((ks * 16 + colB) * 2);
            uint32_t ah[2][4], bh[4][4];
#pragma unroll
            for (int mt = 0; mt < 2; mt++)
                ldsm_x4(ah[mt], st + OFF_A + (uint32_t)((rowA + mt * 16) * ROWB) + aoff);
#pragma unroll
            for (int np = 0; np < 4; np++)
                ldsm_x4(bh[np], st + OFF_B + (uint32_t)((rowB + np * 16) * ROWB) + boff);
#pragma unroll
            for (int mt = 0; mt < 2; mt++)
#pragma unroll
                for (int np = 0; np < 4; np++) {
                    mma_f16(d[mt][np * 2],     ah[mt], bh[np][0], bh[np][1]);
                    mma_f16(d[mt][np * 2 + 1], ah[mt], bh[np][2], bh[np][3]);
                }
        }
        stage++; if (stage >= NSTAGE) stage = 0;
    }

#pragma unroll
    for (int mt = 0; mt < 2; mt++) {
#pragma unroll
        for (int np = 0; np < 4; np++) {
#pragma unroll
            for (int o = 0; o < 2; o++) {
                const float* dd = d[mt][np * 2 + o];
                int nb = n0 + warp_n + np * 16 + o * 8 + 2 * (L & 3);
                float bv0 = __ldg(bias + nb);
                float bv1 = __ldg(bias + nb + 1);
#pragma unroll
                for (int h = 0; h < 2; h++) {
                    int m = m0 + warp_m + mt * 16 + (L >> 2) + h * 8;
                    size_t obase = ((size_t)(m >> 12) << 20) + (size_t)(m & 4095);
                    __stcs(outp + obase + ((size_t)nb << 12), dd[2 * h] + bv0);
                    __stcs(outp + obase + ((size_t)(nb + 1) << 12), dd[2 * h + 1] + bv1);
                }
            }
        }
    }
}

// ---------------------------------------------------------------------------
extern "C" void kernel_launch(void* const* d_in, const int* in_sizes, int n_in,
                              void* d_out, int out_size) {
    const float* position = (const float*)d_in[0];
    const float* gestalt  = (const float*)d_in[1];
    const float* mask     = (const float*)d_in[2];
    const float* depth    = (const float*)d_in[3];
    const float* w1       = (const float*)d_in[4];
    const float* b1       = (const float*)d_in[5];
    const float* w2       = (const float*)d_in[6];
    const float* b2       = (const float*)d_in[7];
    float* out = (float*)d_out;
    (void)in_sizes; (void)n_in; (void)out_size;

    cudaFuncSetAttribute(gemm2_f16, cudaFuncAttributeMaxDynamicSharedMemorySize, SMEM_DYN);
    cudaFuncSetAttribute(fused_h_kernel, cudaFuncAttributeMaxDynamicSharedMemorySize, FH_SMEM);

    __half *w2h, *hh;
    cudaGetSymbolAddress((void**)&w2h, g_W2h);
    cudaGetSymbolAddress((void**)&hh, g_Hh);

    // Launch 1: CX/CY (inline cos)
    cxy_kernel<<<dim3(4, 4, 32), 256>>>(w1, position);
    // Launch 2: U fold + W2 convert (merged)
    misc_kernel<<<64 + (NOUT * HID + 255) / 256, 256>>>(w1, gestalt, w2);
    // Launch 3: fused H (i-split 4-way, unroll 2)
    fused_h_kernel<<<dim3(32, 16, 4), 256, FH_SMEM>>>(mask, depth, w1, b1);
    // Launch 4 (ncu capture slot): gemm2, BK=64 3-stage
    dim3 grid2(NOUT / BN, T_TOK / BM);  // (2, 512)
    gemm2_f16<<<grid2, 256, SMEM_DYN>>>(hh, w2h, HID, HID / BK, b2, out);
}

// round 13
// speedup vs baseline: 1.4571x; 1.2384x over previous
#include <cuda_runtime.h>
#include <cuda_fp16.h>
#include <math.h>
#include <stdint.h>

#define T_TOK 65536      // B * (H/2) * (W/2)
#define K_REAL 1156
#define HID 1024
#define NOUT 256

// ---------------- scratch (device globals; allocation-free) ----------------
__device__ __align__(16) __half g_Hh[(size_t)T_TOK * HID];
__device__ __align__(16) __half g_W2h[NOUT * HID];
__device__ __align__(16) float g_U[16 * 4 * HID];        // [b][s][n]
__device__ __align__(16) float g_CX[16 * 4 * 64 * HID];  // [b][s][j][n]
__device__ __align__(16) float g_CY[16 * 4 * 64 * HID];  // [b][s][i][n]

// ---------------- PTX helpers (baseline PTX only) ----------------
__device__ __forceinline__ uint32_t smem_u32(const void* p) {
    uint32_t a;
    asm("{ .reg .u64 t; cvta.to.shared.u64 t, %1; cvt.u32.u64 %0, t; }"
        : "=r"(a) : "l"(p));
    return a;
}
__device__ __forceinline__ void cp_async16(uint32_t dst, const void* src) {
    asm volatile("cp.async.cg.shared.global [%0], [%1], 16;"
                 :: "r"(dst), "l"(src));
}
#define CP_COMMIT() asm volatile("cp.async.commit_group;" ::: "memory")
#define CP_WAIT(n)  asm volatile("cp.async.wait_group %0;" :: "n"(n) : "memory")

__device__ __forceinline__ void ldsm_x4(uint32_t* r, uint32_t addr) {
    asm volatile("ldmatrix.sync.aligned.m8n8.x4.shared.b16 {%0,%1,%2,%3}, [%4];"
                 : "=r"(r[0]), "=r"(r[1]), "=r"(r[2]), "=r"(r[3]) : "r"(addr));
}
__device__ __forceinline__ void mma_f16(float* d, const uint32_t* a,
                                        uint32_t b0, uint32_t b1) {
    asm volatile("mma.sync.aligned.m16n8k16.row.col.f32.f16.f16.f32 "
                 "{%0,%1,%2,%3}, {%4,%5,%6,%7}, {%8,%9}, {%0,%1,%2,%3};"
                 : "+f"(d[0]), "+f"(d[1]), "+f"(d[2]), "+f"(d[3])
                 : "r"(a[0]), "r"(a[1]), "r"(a[2]), "r"(a[3]), "r"(b0), "r"(b1));
}
// pack two fp32 -> fp16x2 (lo = first arg)
__device__ __forceinline__ uint32_t pack_f16x2(float lo, float hi) {
    uint32_t r;
    asm("cvt.rn.f16x2.f32 %0, %1, %2;" : "=r"(r) : "f"(hi), "f"(lo));
    return r;
}

// ---------------------------------------------------------------------------
// Launch 1: merged setup kernel.
// Blocks [0,512): CX/CY fold (inline cos table, bit-exact fp32 arg chain).
// Blocks [512,576): U fold.  Blocks [576,1600): W2 fp16 convert.
// ---------------------------------------------------------------------------
__global__ void setup_kernel(const float* __restrict__ w1,
                             const float* __restrict__ pos,
                             const float* __restrict__ gestalt,
                             const float* __restrict__ w2) {
    int bxg = blockIdx.x;
    if (bxg < 512) {
        // ---- CX/CY fold (exact cxy_kernel body) ----
        __shared__ float scos[1024];   // [f][j] for this (ax, b, sub)
        int n = (bxg & 3) * 256 + threadIdx.x;
        int s = (bxg >> 2) & 3;
        int bz = bxg >> 4;
        int b = bz & 15;
        int ax = bz >> 4;
        int sub = ax ? (s >> 1) : (s & 1);

        {
            const float HALF_PI = 1.57079632679489661923f;
            float pw = pos[b * 4 + 3];
            float stdv = __fdiv_rn(0.1f, fminf(fmaxf(pw, 0.0078125f), 0.5f));
            float ctr = fminf(fmaxf(pos[b * 4 + (ax ? 1 : 0)], -1.f), 1.f);
#pragma unroll
            for (int k = 0; k < 4; k++) {
                int idx = threadIdx.x + k * 256;
                int f = idx >> 6;
                int j = idx & 63;
                int w = 2 * j + sub;
                float g = __fsub_rn(__fmul_rn(__fdiv_rn((float)w, 127.0f), 2.0f), 1.0f);
                float fs = (float)(1 << f);
                float a = __fmul_rn(__fmul_rn(__fmul_rn(__fsub_rn(g, ctr), stdv), HALF_PI), fs);
                scos[idx] = (float)cos((double)a);
            }
        }
        __syncthreads();

        float w[16];
        size_t base = (size_t)n * K_REAL + 1024 + (ax ? 4 : 0) + s;
#pragma unroll
        for (int f = 0; f < 16; f++) w[f] = w1[base + 8 * f];
        float* outp = (ax ? g_CY : g_CX) + ((size_t)(b * 4 + s) * 64) * HID + n;
#pragma unroll 2
        for (int j = 0; j < 64; j++) {
            float acc = 0.f;
#pragma unroll
            for (int f = 0; f < 16; f++) acc += w[f] * scos[f * 64 + j];
            outp[(size_t)j * HID] = acc;
        }
    } else if (bxg < 576) {
        // ---- U fold ----
        int bx = bxg - 512;
        int n = (bx & 3) * 256 + threadIdx.x;
        int b = bx >> 2;
        const float4* wrow = (const float4*)(w1 + (size_t)n * K_REAL);
        const float* g = gestalt + b * 256;
        float a0 = 0.f, a1 = 0.f, a2 = 0.f, a3 = 0.f;
#pragma unroll 4
        for (int c = 0; c < 256; c++) {
            float4 w = wrow[c];
            float gv = g[c];
            a0 += w.x * gv; a1 += w.y * gv; a2 += w.z * gv; a3 += w.w * gv;
        }
        g_U[(b * 4 + 0) * HID + n] = a0;
        g_U[(b * 4 + 1) * HID + n] = a1;
        g_U[(b * 4 + 2) * HID + n] = a2;
        g_U[(b * 4 + 3) * HID + n] = a3;
    } else {
        // ---- W2 fp16 convert ----
        int idx = (bxg - 576) * 256 + threadIdx.x;
        if (idx < NOUT * HID) g_W2h[idx] = __float2half_rn(w2[idx]);
    }
}

// ---------------------------------------------------------------------------
// Launch 2: Fused H, i-split 4-way (exact R10/R12 body — verified 100us)
// ---------------------------------------------------------------------------
#define FH_SMEM (10528 * 4)

__global__ __launch_bounds__(256, 3) void fused_h_kernel(
    const float* __restrict__ mask, const float* __restrict__ depth,
    const float* __restrict__ w1, const float* __restrict__ b1) {
    extern __shared__ float sm[];
    float* sCX = sm;              // [s][j(64)][nl(32)]
    float* sCY = sm + 8192;       // [s][il(16)][nl(32)]
    float* sU  = sm + 10240;      // [s][nl]
    float* sWd = sm + 10368;      // [s][nl]
    float* sB  = sm + 10496;      // [nl]

    const int b  = blockIdx.y;
    const int n0 = blockIdx.x * 32;
    const int iz = blockIdx.z;
    const int tid = threadIdx.x;

    for (int idx = tid; idx < 8192; idx += 256) {
        int nl = idx & 31, j = (idx >> 5) & 63, s = idx >> 11;
        sCX[idx] = g_CX[((size_t)(b * 4 + s) * 64 + j) * HID + n0 + nl];
    }
    for (int idx = tid; idx < 2048; idx += 256) {
        int nl = idx & 31, il = (idx >> 5) & 15, s = idx >> 9;
        sCY[idx] = g_CY[((size_t)(b * 4 + s) * 64 + iz * 16 + il) * HID + n0 + nl];
    }
    if (tid < 128) {
        int s = tid >> 5, nl = tid & 31;
        sU[tid]  = g_U[(b * 4 + s) * HID + n0 + nl];
        sWd[tid] = w1[(size_t)(n0 + nl) * K_REAL + 1152 + s];
    }
    if (tid < 32) sB[tid] = b1[n0 + tid];
    __syncthreads();

    const int npl = (tid & 7) * 4;     // 4 consecutive n
    const int tg  = tid >> 3;          // 0..31
    const int il  = tg & 15;           // i within split
    const int jh  = tg >> 4;           // j half (0/1)
    const int i   = iz * 16 + il;

    float uc[4][4], wds[4][4], bbs[4];
#pragma unroll
    for (int s = 0; s < 4; s++) {
        float4 tu = *(float4*)&sU[s * 32 + npl];
        float4 tc = *(float4*)&sCY[s * 512 + il * 32 + npl];
        uc[s][0] = tu.x + tc.x; uc[s][1] = tu.y + tc.y;
        uc[s][2] = tu.z + tc.z; uc[s][3] = tu.w + tc.w;
        float4 tw = *(float4*)&sWd[s * 32 + npl];
        wds[s][0] = tw.x; wds[s][1] = tw.y; wds[s][2] = tw.z; wds[s][3] = tw.w;
    }
    {
        float4 tb = *(float4*)&sB[npl];
        bbs[0] = tb.x; bbs[1] = tb.y; bbs[2] = tb.z; bbs[3] = tb.w;
    }

    const float* mrow = mask  + b * 16384 + i * 256 + jh * 64;
    const float* drow = depth + b * 16384 + i * 256 + jh * 64;
    const float* cxb  = sCX + (jh * 32) * 32 + npl;
    size_t rowbase = ((size_t)(b * 4096 + i * 64 + jh * 32)) * HID + n0 + npl;

#pragma unroll 2
    for (int jp = 0; jp < 16; jp++) {      // 2 j per iteration
        float4 mv0 = *(const float4*)&mrow[jp * 4];
        float4 mv1 = *(const float4*)&mrow[jp * 4 + 128];
        float4 dv0 = *(const float4*)&drow[jp * 4];
        float4 dv1 = *(const float4*)&drow[jp * 4 + 128];
#pragma unroll
        for (int t = 0; t < 2; t++) {
            float m00 = t ? mv0.z : mv0.x;
            float m01 = t ? mv0.w : mv0.y;
            float m10 = t ? mv1.z : mv1.x;
            float m11 = t ? mv1.w : mv1.y;
            float d00 = t ? dv0.z : dv0.x;
            float d01 = t ? dv0.w : dv0.y;
            float d10 = t ? dv1.z : dv1.x;
            float d11 = t ? dv1.w : dv1.y;
            int jl = jp * 2 + t;
            float4 cx0 = *(float4*)&cxb[0 * 2048 + jl * 32];
            float4 cx1 = *(float4*)&cxb[1 * 2048 + jl * 32];
            float4 cx2 = *(float4*)&cxb[2 * 2048 + jl * 32];
            float4 cx3 = *(float4*)&cxb[3 * 2048 + jl * 32];
            float cxs[4][4];
            cxs[0][0] = cx0.x; cxs[0][1] = cx0.y; cxs[0][2] = cx0.z; cxs[0][3] = cx0.w;
            cxs[1][0] = cx1.x; cxs[1][1] = cx1.y; cxs[1][2] = cx1.z; cxs[1][3] = cx1.w;
            cxs[2][0] = cx2.x; cxs[2][1] = cx2.y; cxs[2][2] = cx2.z; cxs[2][3] = cx2.w;
            cxs[3][0] = cx3.x; cxs[3][1] = cx3.y; cxs[3][2] = cx3.z; cxs[3][3] = cx3.w;
            float v[4];
#pragma unroll
            for (int q = 0; q < 4; q++) {
                float h = bbs[q];
                h += m00 * (uc[0][q] + cxs[0][q] + d00 * wds[0][q]);
                h += m01 * (uc[1][q] + cxs[1][q] + d01 * wds[1][q]);
                h += m10 * (uc[2][q] + cxs[2][q] + d10 * wds[2][q]);
                h += m11 * (uc[3][q] + cxs[3][q] + d11 * wds[3][q]);
                v[q] = __fdividef(h, 1.0f + __expf(-h));
            }
            uint2 o;
            o.x = pack_f16x2(v[0], v[1]);
            o.y = pack_f16x2(v[2], v[3]);
            __stcs((uint2*)(g_Hh + rowbase + (size_t)jl * HID), o);
        }
    }
}

// ---------------------------------------------------------------------------
// Launch 3: single-pass fp16 GEMM, BK=64, 3-stage (exact R11/R12 — 104us).
// ---------------------------------------------------------------------------
#define BM 128
#define BN 128
#define BK 64
#define ROWB 144                 // 128B data + 16B pad
#define TILE_B (BM * ROWB)       // 18432
#define OFF_A 0
#define OFF_B TILE_B
#define STAGE_B (2 * TILE_B)     // 36864
#define NSTAGE 3
#define SMEM_DYN (NSTAGE * STAGE_B)  // 110592

__device__ __forceinline__ void cp_chunk(uint32_t st,
                                         const __half* A, const __half* B,
                                         int K, int k0, int tid) {
#pragma unroll
    for (int it = 0; it < 4; it++) {
        int idx = tid + it * 256;         // 0..1023
        int r = idx >> 3, q = idx & 7;    // row 0..127, 16B seg 0..7
        uint32_t o = (uint32_t)(r * ROWB + q * 16);
        size_t so = (size_t)r * K + k0 + q * 8;
        cp_async16(st + OFF_A + o, A + so);
        cp_async16(st + OFF_B + o, B + so);
    }
}

__global__ __launch_bounds__(256, 2) void gemm2_f16(
    const __half* __restrict__ A_g, const __half* __restrict__ B_g,
    int K, int NCH, const float* __restrict__ bias, float* __restrict__ outp) {
    extern __shared__ char dsm[];
    uint32_t sb = smem_u32(dsm);

    const int tid = threadIdx.x;
    const int wid = tid >> 5;
    const int L = tid & 31;
    const int m0 = blockIdx.y * BM;
    const int n0 = blockIdx.x * BN;
    const int warp_m = (wid >> 1) * 32;
    const int warp_n = (wid & 1) * 64;

    const __half* A = A_g + (size_t)m0 * K;
    const __half* B = B_g + (size_t)n0 * K;

    const int rowA = warp_m + (L & 7) + ((L >> 3) & 1) * 8;
    const int colA = (L >> 4) * 8;
    const int rowB = warp_n + (L & 7) + (L >> 4) * 8;
    const int colB = ((L >> 3) & 1) * 8;

    float d[2][8][4];
#pragma unroll
    for (int i = 0; i < 2; i++)
#pragma unroll
        for (int j = 0; j < 8; j++)
#pragma unroll
            for (int e = 0; e < 4; e++) d[i][j][e] = 0.0f;

#pragma unroll
    for (int p = 0; p < NSTAGE - 1; p++) {
        cp_chunk(sb + p * STAGE_B, A, B, K, p * BK, tid);
        CP_COMMIT();
    }

    int stage = 0;
    for (int c = 0; c < NCH; c++) {
        if (c + 1 < NCH) { CP_WAIT(1); } else { CP_WAIT(0); }
        __syncthreads();
        if (c + NSTAGE - 1 < NCH) {
            int ps = stage + NSTAGE - 1; if (ps >= NSTAGE) ps -= NSTAGE;
            cp_chunk(sb + ps * STAGE_B, A, B, K, (c + NSTAGE - 1) * BK, tid);
            CP_COMMIT();
        }

        uint32_t st = sb + stage * STAGE_B;
#pragma unroll
        for (int ks = 0; ks < 4; ks++) {
            uint32_t aoff = (uint32_t)((ks * 16 + colA) * 2);
            uint32_t boff = (uint32_t)((ks * 16 + colB) * 2);
            uint32_t ah[2][4], bh[4][4];
#pragma unroll
            for (int mt = 0; mt < 2; mt++)
                ldsm_x4(ah[mt], st + OFF_A + (uint32_t)((rowA + mt * 16) * ROWB) + aoff);
#pragma unroll
            for (int np = 0; np < 4; np++)
                ldsm_x4(bh[np], st + OFF_B + (uint32_t)((rowB + np * 16) * ROWB) + boff);
#pragma unroll
            for (int mt = 0; mt < 2; mt++)
#pragma unroll
                for (int np = 0; np < 4; np++) {
                    mma_f16(d[mt][np * 2],     ah[mt], bh[np][0], bh[np][1]);
                    mma_f16(d[mt][np * 2 + 1], ah[mt], bh[np][2], bh[np][3]);
                }
        }
        stage++; if (stage >= NSTAGE) stage = 0;
    }

#pragma unroll
    for (int mt = 0; mt < 2; mt++) {
#pragma unroll
        for (int np = 0; np < 4; np++) {
#pragma unroll
            for (int o = 0; o < 2; o++) {
                const float* dd = d[mt][np * 2 + o];
                int nb = n0 + warp_n + np * 16 + o * 8 + 2 * (L & 3);
                float bv0 = __ldg(bias + nb);
                float bv1 = __ldg(bias + nb + 1);
#pragma unroll
                for (int h = 0; h < 2; h++) {
                    int m = m0 + warp_m + mt * 16 + (L >> 2) + h * 8;
                    size_t obase = ((size_t)(m >> 12) << 20) + (size_t)(m & 4095);
                    __stcs(outp + obase + ((size_t)nb << 12), dd[2 * h] + bv0);
                    __stcs(outp + obase + ((size_t)(nb + 1) << 12), dd[2 * h + 1] + bv1);
                }
            }
        }
    }
}

// ---------------------------------------------------------------------------
extern "C" void kernel_launch(void* const* d_in, const int* in_sizes, int n_in,
                              void* d_out, int out_size) {
    const float* position = (const float*)d_in[0];
    const float* gestalt  = (const float*)d_in[1];
    const float* mask     = (const float*)d_in[2];
    const float* depth    = (const float*)d_in[3];
    const float* w1       = (const float*)d_in[4];
    const float* b1       = (const float*)d_in[5];
    const float* w2       = (const float*)d_in[6];
    const float* b2       = (const float*)d_in[7];
    float* out = (float*)d_out;
    (void)in_sizes; (void)n_in; (void)out_size;

    cudaFuncSetAttribute(gemm2_f16, cudaFuncAttributeMaxDynamicSharedMemorySize, SMEM_DYN);
    cudaFuncSetAttribute(fused_h_kernel, cudaFuncAttributeMaxDynamicSharedMemorySize, FH_SMEM);

    __half *w2h, *hh;
    cudaGetSymbolAddress((void**)&w2h, g_W2h);
    cudaGetSymbolAddress((void**)&hh, g_Hh);

    // Launch 1: merged setup (CX/CY + U + W2)
    setup_kernel<<<576 + (NOUT * HID + 255) / 256, 256>>>(w1, position, gestalt, w2);
    // Launch 2: fused H (i-split 4-way, unroll 2)
    fused_h_kernel<<<dim3(32, 16, 4), 256, FH_SMEM>>>(mask, depth, w1, b1);
    // Launch 3: gemm2, BK=64 3-stage
    dim3 grid2(NOUT / BN, T_TOK / BM);  // (2, 512)
    gemm2_f16<<<grid2, 256, SMEM_DYN>>>(hh, w2h, HID, HID / BK, b2, out);
}